// round 4
// baseline (speedup 1.0000x reference)
#include <cuda_runtime.h>

// Heston Monte Carlo: 65536 paths x 512 steps.
// Inputs:  d_in[0] = Z_vol  [65536, 512, 2] f32 (only [:,:,0] used)
//          d_in[1] = Z_price[65536, 512]    f32
// Output:  d_out = S [65536,513] f32 followed by V [65536,513] f32

#define NSTEPS   512
#define NP1      513
#define BATCH    65536
#define TPB      128
#define CHUNK    32
#define NCHUNKS  (NSTEPS / CHUNK)
#define SROW     (CHUNK + 1)   // smem row pitch (pad to kill bank conflicts)

__global__ __launch_bounds__(TPB) void heston_kernel(
    const float2* __restrict__ zvol,    // [BATCH][NSTEPS] float2
    const float*  __restrict__ zprice,  // [BATCH][NSTEPS]
    float* __restrict__ S_out,          // [BATCH][NP1]
    float* __restrict__ V_out)          // [BATCH][NP1]
{
    __shared__ float bufA[TPB * SROW];  // zv tile  -> S tile (in-place)
    __shared__ float bufB[TPB * SROW];  // zp tile  -> V tile (in-place)

    const int tid = threadIdx.x;
    const long long pbase  = (long long)blockIdx.x * TPB;
    const long long mypath = pbase + tid;

    // model constants
    const float dt       = 1.0f / 512.0f;
    const float sqrt_dt  = 0.04419417382415922f;     // sqrt(1/512)
    const float rho      = -0.7f;
    const float rho_perp = 0.7141428428542850f;      // sqrt(0.51)
    const float V0f      = 0.055225f;                 // 0.235^2
    const float kth_dt   = 0.04f * dt;                // KAPPA*THETA*dt (KAPPA=1)
    const float two_sdt  = 2.0f * sqrt_dt;            // SIGMA_V * sqrt_dt

    // t = 0 column (small, uncoalesced, negligible traffic)
    S_out[mypath * NP1] = 100.0f;
    V_out[mypath * NP1] = V0f;

    float V    = V0f;
    float logS = 0.0f;

    float* myA = &bufA[tid * SROW];
    float* myB = &bufB[tid * SROW];

    for (int ck = 0; ck < NCHUNKS; ck++) {
        const int t0 = ck * CHUNK;

        // ---- cooperative coalesced load: each warp reads one path's row chunk ----
        #pragma unroll
        for (int i = tid; i < TPB * CHUNK; i += TPB) {
            const int row = i >> 5;    // path within block
            const int col = i & 31;    // step within chunk
            const long long g = (pbase + row) * (long long)NSTEPS + t0 + col;
            float2 zv2 = zvol[g];                 // 256B/row coalesced, keep .x
            bufA[row * SROW + col] = zv2.x;
            bufB[row * SROW + col] = zprice[g];   // 128B/row coalesced
        }
        __syncthreads();

        // ---- compute: thread owns its path row; overwrite smem with S/V ----
        #pragma unroll
        for (int c = 0; c < CHUNK; c++) {
            const float zv = myA[c];
            const float zp = myB[c];

            const float Vpos = fmaxf(V, 0.0f);
            const float sv   = sqrtf(Vpos);                       // sqrt(V_pos)
            // V_next = V + (theta - Vpos)*dt + 2*sqrt(Vpos*dt)*zv
            float Vnext = fmaf(two_sdt * zv, sv, fmaf(-dt, Vpos, V + kth_dt));
            Vnext = fmaxf(Vnext, 0.0f);

            const float dB = sqrt_dt * fmaf(rho, zv, rho_perp * zp);
            logS = fmaf(sv, dB, fmaf(-0.5f * dt, Vpos, logS));

            myA[c] = 100.0f * __expf(logS);   // S
            myB[c] = Vnext;                   // V
            V = Vnext;
        }
        __syncthreads();

        // ---- cooperative coalesced store ----
        #pragma unroll
        for (int i = tid; i < TPB * CHUNK; i += TPB) {
            const int row = i >> 5;
            const int col = i & 31;
            const long long o = (pbase + row) * (long long)NP1 + (t0 + 1 + col);
            S_out[o] = bufA[row * SROW + col];
            V_out[o] = bufB[row * SROW + col];
        }
        __syncthreads();
    }
}

extern "C" void kernel_launch(void* const* d_in, const int* in_sizes, int n_in,
                              void* d_out, int out_size) {
    const float2* zvol   = (const float2*)d_in[0];
    const float*  zprice = (const float*) d_in[1];
    float* S = (float*)d_out;
    float* Vv = S + (size_t)BATCH * NP1;

    heston_kernel<<<BATCH / TPB, TPB>>>(zvol, zprice, S, Vv);
}

// round 5
// speedup vs baseline: 1.0024x; 1.0024x over previous
#include <cuda_runtime.h>

// Heston Monte Carlo: 65536 paths x 512 steps.
// Inputs:  d_in[0] = Z_vol  [65536, 512, 2] f32 (only [:,:,0] used)
//          d_in[1] = Z_price[65536, 512]    f32
// Output:  d_out = S [65536,513] f32 followed by V [65536,513] f32

#define NSTEPS   512
#define NP1      513
#define BATCH    65536
#define TPB      128
#define CHUNK    32
#define NCHUNKS  (NSTEPS / CHUNK)
#define SROW     (CHUNK + 1)   // smem row pitch (pad to kill bank conflicts)

__global__ __launch_bounds__(TPB) void heston_kernel(
    const float2* __restrict__ zvol,    // [BATCH][NSTEPS] float2
    const float*  __restrict__ zprice,  // [BATCH][NSTEPS]
    float* __restrict__ S_out,          // [BATCH][NP1]
    float* __restrict__ V_out)          // [BATCH][NP1]
{
    __shared__ float bufA[TPB * SROW];  // zv tile  -> S tile (in-place)
    __shared__ float bufB[TPB * SROW];  // zp tile  -> V tile (in-place)

    const int tid = threadIdx.x;
    const long long pbase  = (long long)blockIdx.x * TPB;
    const long long mypath = pbase + tid;

    // model constants
    const float dt       = 1.0f / 512.0f;
    const float sqrt_dt  = 0.04419417382415922f;     // sqrt(1/512)
    const float rho      = -0.7f;
    const float rho_perp = 0.7141428428542850f;      // sqrt(0.51)
    const float V0f      = 0.055225f;                 // 0.235^2
    const float kth_dt   = 0.04f * dt;                // KAPPA*THETA*dt (KAPPA=1)
    const float two_sdt  = 2.0f * sqrt_dt;            // SIGMA_V * sqrt_dt

    // t = 0 column (small, uncoalesced, negligible traffic)
    S_out[mypath * NP1] = 100.0f;
    V_out[mypath * NP1] = V0f;

    float V    = V0f;
    float logS = 0.0f;

    float* myA = &bufA[tid * SROW];
    float* myB = &bufB[tid * SROW];

    for (int ck = 0; ck < NCHUNKS; ck++) {
        const int t0 = ck * CHUNK;

        // ---- cooperative coalesced load: each warp reads one path's row chunk ----
        #pragma unroll
        for (int i = tid; i < TPB * CHUNK; i += TPB) {
            const int row = i >> 5;    // path within block
            const int col = i & 31;    // step within chunk
            const long long g = (pbase + row) * (long long)NSTEPS + t0 + col;
            float2 zv2 = zvol[g];                 // 256B/row coalesced, keep .x
            bufA[row * SROW + col] = zv2.x;
            bufB[row * SROW + col] = zprice[g];   // 128B/row coalesced
        }
        __syncthreads();

        // ---- compute: thread owns its path row; overwrite smem with S/V ----
        #pragma unroll
        for (int c = 0; c < CHUNK; c++) {
            const float zv = myA[c];
            const float zp = myB[c];

            const float Vpos = fmaxf(V, 0.0f);
            const float sv   = sqrtf(Vpos);                       // sqrt(V_pos)
            // V_next = V + (theta - Vpos)*dt + 2*sqrt(Vpos*dt)*zv
            float Vnext = fmaf(two_sdt * zv, sv, fmaf(-dt, Vpos, V + kth_dt));
            Vnext = fmaxf(Vnext, 0.0f);

            const float dB = sqrt_dt * fmaf(rho, zv, rho_perp * zp);
            logS = fmaf(sv, dB, fmaf(-0.5f * dt, Vpos, logS));

            myA[c] = 100.0f * __expf(logS);   // S
            myB[c] = Vnext;                   // V
            V = Vnext;
        }
        __syncthreads();

        // ---- cooperative coalesced store ----
        #pragma unroll
        for (int i = tid; i < TPB * CHUNK; i += TPB) {
            const int row = i >> 5;
            const int col = i & 31;
            const long long o = (pbase + row) * (long long)NP1 + (t0 + 1 + col);
            S_out[o] = bufA[row * SROW + col];
            V_out[o] = bufB[row * SROW + col];
        }
        __syncthreads();
    }
}

extern "C" void kernel_launch(void* const* d_in, const int* in_sizes, int n_in,
                              void* d_out, int out_size) {
    const float2* zvol   = (const float2*)d_in[0];
    const float*  zprice = (const float*) d_in[1];
    float* S = (float*)d_out;
    float* Vv = S + (size_t)BATCH * NP1;

    heston_kernel<<<BATCH / TPB, TPB>>>(zvol, zprice, S, Vv);
}

// round 6
// speedup vs baseline: 1.0027x; 1.0003x over previous
#include <cuda_runtime.h>

// Heston Monte Carlo: 65536 paths x 512 steps.
// Inputs:  d_in[0] = Z_vol  [65536, 512, 2] f32 (only [:,:,0] used)
//          d_in[1] = Z_price[65536, 512]    f32
// Output:  d_out = S [65536,513] f32 followed by V [65536,513] f32

#define NSTEPS   512
#define NP1      513
#define BATCH    65536
#define TPB      128
#define CHUNK    32
#define NCHUNKS  (NSTEPS / CHUNK)
#define SROW     (CHUNK + 1)   // smem row pitch (pad to kill bank conflicts)

__global__ __launch_bounds__(TPB) void heston_kernel(
    const float2* __restrict__ zvol,    // [BATCH][NSTEPS] float2
    const float*  __restrict__ zprice,  // [BATCH][NSTEPS]
    float* __restrict__ S_out,          // [BATCH][NP1]
    float* __restrict__ V_out)          // [BATCH][NP1]
{
    __shared__ float bufA[TPB * SROW];  // zv tile  -> S tile (in-place)
    __shared__ float bufB[TPB * SROW];  // zp tile  -> V tile (in-place)

    const int tid = threadIdx.x;
    const long long pbase  = (long long)blockIdx.x * TPB;
    const long long mypath = pbase + tid;

    // model constants
    const float dt       = 1.0f / 512.0f;
    const float sqrt_dt  = 0.04419417382415922f;     // sqrt(1/512)
    const float rho      = -0.7f;
    const float rho_perp = 0.7141428428542850f;      // sqrt(0.51)
    const float V0f      = 0.055225f;                 // 0.235^2
    const float kth_dt   = 0.04f * dt;                // KAPPA*THETA*dt (KAPPA=1)
    const float two_sdt  = 2.0f * sqrt_dt;            // SIGMA_V * sqrt_dt

    // t = 0 column (small, uncoalesced, negligible traffic)
    S_out[mypath * NP1] = 100.0f;
    V_out[mypath * NP1] = V0f;

    float V    = V0f;
    float logS = 0.0f;

    float* myA = &bufA[tid * SROW];
    float* myB = &bufB[tid * SROW];

    for (int ck = 0; ck < NCHUNKS; ck++) {
        const int t0 = ck * CHUNK;

        // ---- cooperative coalesced load: each warp reads one path's row chunk ----
        #pragma unroll
        for (int i = tid; i < TPB * CHUNK; i += TPB) {
            const int row = i >> 5;    // path within block
            const int col = i & 31;    // step within chunk
            const long long g = (pbase + row) * (long long)NSTEPS + t0 + col;
            float2 zv2 = zvol[g];                 // 256B/row coalesced, keep .x
            bufA[row * SROW + col] = zv2.x;
            bufB[row * SROW + col] = zprice[g];   // 128B/row coalesced
        }
        __syncthreads();

        // ---- compute: thread owns its path row; overwrite smem with S/V ----
        #pragma unroll
        for (int c = 0; c < CHUNK; c++) {
            const float zv = myA[c];
            const float zp = myB[c];

            const float Vpos = fmaxf(V, 0.0f);
            const float sv   = sqrtf(Vpos);                       // sqrt(V_pos)
            // V_next = V + (theta - Vpos)*dt + 2*sqrt(Vpos*dt)*zv
            float Vnext = fmaf(two_sdt * zv, sv, fmaf(-dt, Vpos, V + kth_dt));
            Vnext = fmaxf(Vnext, 0.0f);

            const float dB = sqrt_dt * fmaf(rho, zv, rho_perp * zp);
            logS = fmaf(sv, dB, fmaf(-0.5f * dt, Vpos, logS));

            myA[c] = 100.0f * __expf(logS);   // S
            myB[c] = Vnext;                   // V
            V = Vnext;
        }
        __syncthreads();

        // ---- cooperative coalesced store ----
        #pragma unroll
        for (int i = tid; i < TPB * CHUNK; i += TPB) {
            const int row = i >> 5;
            const int col = i & 31;
            const long long o = (pbase + row) * (long long)NP1 + (t0 + 1 + col);
            S_out[o] = bufA[row * SROW + col];
            V_out[o] = bufB[row * SROW + col];
        }
        __syncthreads();
    }
}

extern "C" void kernel_launch(void* const* d_in, const int* in_sizes, int n_in,
                              void* d_out, int out_size) {
    const float2* zvol   = (const float2*)d_in[0];
    const float*  zprice = (const float*) d_in[1];
    float* S = (float*)d_out;
    float* Vv = S + (size_t)BATCH * NP1;

    heston_kernel<<<BATCH / TPB, TPB>>>(zvol, zprice, S, Vv);
}